// round 1
// baseline (speedup 1.0000x reference)
#include <cuda_runtime.h>

#define EMBED   1024
#define HEADS   16
#define DH      64
#define NSEQ    2048
#define BATCH   2
#define ROWS    (BATCH * NSEQ)          // 4096
#define QKV_COLS (3 * EMBED)            // 3072
#define ATTN_SCALE 0.125f               // 64^-0.5

// Scratch (allocation-free rule: __device__ globals)
__device__ float g_qkv[(size_t)ROWS * QKV_COLS];   // 50.3 MB
__device__ float g_att[(size_t)ROWS * EMBED];      // 16.8 MB

// ---------------------------------------------------------------------------
// SGEMM: C[M][N] = A[M][K] @ B[N][K]^T + bias[N]
// Block tile 128x128, K-tile 32, 256 threads, 8x8 per-thread register tile.
// A and B are both row-major with K contiguous; tiles are transposed into
// smem ([k][m] / [k][n], stride 132) so the inner loop is rank-1 updates with
// float4 smem reads (4 LDS.128 per 64 FFMA).
// ---------------------------------------------------------------------------
__global__ __launch_bounds__(256) void sgemm_bt(
    const float* __restrict__ A, const float* __restrict__ B,
    const float* __restrict__ bias, float* __restrict__ C,
    int M, int N, int K)
{
    __shared__ float As[32 * 132];
    __shared__ float Bs[32 * 132];

    const int t  = threadIdx.x;
    const int tx = t & 15;
    const int ty = t >> 4;
    const int bm = blockIdx.y << 7;
    const int bn = blockIdx.x << 7;

    float acc[8][8];
#pragma unroll
    for (int i = 0; i < 8; i++)
#pragma unroll
        for (int j = 0; j < 8; j++) acc[i][j] = 0.0f;

    const float* Ab = A + (size_t)bm * K;
    const float* Bb = B + (size_t)bn * K;

    for (int kt = 0; kt < K; kt += 32) {
        // Load + transpose 128x32 tiles of A and B. 1024 float4 per matrix,
        // 256 threads -> 4 float4 each. Coalesced: 8 threads cover a 128B row chunk.
#pragma unroll
        for (int i = 0; i < 4; i++) {
            int idx = (i << 8) + t;
            int r   = idx >> 3;        // 0..127
            int kv  = idx & 7;         // 0..7 (float4 index within K-tile)
            float4 av = *(const float4*)(Ab + (size_t)r * K + kt + (kv << 2));
            As[(kv * 4 + 0) * 132 + r] = av.x;
            As[(kv * 4 + 1) * 132 + r] = av.y;
            As[(kv * 4 + 2) * 132 + r] = av.z;
            As[(kv * 4 + 3) * 132 + r] = av.w;
            float4 bv = *(const float4*)(Bb + (size_t)r * K + kt + (kv << 2));
            Bs[(kv * 4 + 0) * 132 + r] = bv.x;
            Bs[(kv * 4 + 1) * 132 + r] = bv.y;
            Bs[(kv * 4 + 2) * 132 + r] = bv.z;
            Bs[(kv * 4 + 3) * 132 + r] = bv.w;
        }
        __syncthreads();

#pragma unroll 8
        for (int k = 0; k < 32; k++) {
            float4 a0 = *(const float4*)&As[k * 132 + (ty << 2)];
            float4 a1 = *(const float4*)&As[k * 132 + 64 + (ty << 2)];
            float4 b0 = *(const float4*)&Bs[k * 132 + (tx << 2)];
            float4 b1 = *(const float4*)&Bs[k * 132 + 64 + (tx << 2)];
            float ar[8] = {a0.x, a0.y, a0.z, a0.w, a1.x, a1.y, a1.z, a1.w};
            float br[8] = {b0.x, b0.y, b0.z, b0.w, b1.x, b1.y, b1.z, b1.w};
#pragma unroll
            for (int i = 0; i < 8; i++)
#pragma unroll
                for (int j = 0; j < 8; j++)
                    acc[i][j] += ar[i] * br[j];
        }
        __syncthreads();
    }

    // Epilogue: add bias, write float4s (coalesced across tx).
#pragma unroll
    for (int i = 0; i < 8; i++) {
        int r = bm + ((i < 4) ? ((ty << 2) + i) : (64 + (ty << 2) + i - 4));
#pragma unroll
        for (int jg = 0; jg < 2; jg++) {
            int c = bn + (jg << 6) + (tx << 2);
            float4 bo = *(const float4*)(bias + c);
            float4 o;
            o.x = acc[i][jg * 4 + 0] + bo.x;
            o.y = acc[i][jg * 4 + 1] + bo.y;
            o.z = acc[i][jg * 4 + 2] + bo.z;
            o.w = acc[i][jg * 4 + 3] + bo.w;
            *(float4*)(C + (size_t)r * N + c) = o;
        }
    }
}

// ---------------------------------------------------------------------------
// Fused flash attention, fp32, online softmax.
// Block: one (b,h) pair x 64-query tile. 256 threads = 16(tx: key/dim cols) x
// 16(ty: query rows), 4x4 register tiles. Dh = 64 fully inside smem tiles.
// Smem: Qt[d][q], Kt[d][k] (transposed), Vs[k][d], Pt[k][q]; stride 68.
// ---------------------------------------------------------------------------
#define AS 68          // smem row stride (floats)
#define TILE_F (64 * AS)

__device__ __forceinline__ void load_tile_T(float* St, const float* g, int ldg) {
    // 64 rows x 64 cols, transpose into St[d][r], stride AS
    int t = threadIdx.x;
#pragma unroll
    for (int i = 0; i < 4; i++) {
        int idx = (i << 8) + t;
        int r   = idx >> 4;     // 0..63
        int dv  = idx & 15;     // float4 index along d
        float4 v = *(const float4*)(g + (size_t)r * ldg + (dv << 2));
        St[(dv * 4 + 0) * AS + r] = v.x;
        St[(dv * 4 + 1) * AS + r] = v.y;
        St[(dv * 4 + 2) * AS + r] = v.z;
        St[(dv * 4 + 3) * AS + r] = v.w;
    }
}

__device__ __forceinline__ void load_tile_N(float* St, const float* g, int ldg) {
    // 64 rows x 64 cols, natural layout St[r][d], stride AS
    int t = threadIdx.x;
#pragma unroll
    for (int i = 0; i < 4; i++) {
        int idx = (i << 8) + t;
        int r   = idx >> 4;
        int dv  = idx & 15;
        float4 v = *(const float4*)(g + (size_t)r * ldg + (dv << 2));
        *(float4*)&St[r * AS + (dv << 2)] = v;
    }
}

__global__ __launch_bounds__(256) void attn_kernel(
    const float* __restrict__ qkv, float* __restrict__ out)
{
    const int bh = blockIdx.x;          // 0..31
    const int b  = bh >> 4;
    const int h  = bh & 15;
    const int qt = blockIdx.y;          // 0..31

    extern __shared__ float sm[];
    float* Qt = sm;                     // [d][q]
    float* Kt = sm + TILE_F;            // [d][k]
    float* Vs = sm + 2 * TILE_F;        // [k][d]
    float* Pt = sm + 3 * TILE_F;        // [k][q]

    const int t  = threadIdx.x;
    const int tx = t & 15;              // key col / out dim group
    const int ty = t >> 4;              // query row group

    const float* qbase = qkv + ((size_t)(b * NSEQ + qt * 64)) * QKV_COLS + h * DH;
    load_tile_T(Qt, qbase, QKV_COLS);

    float m[4], l[4], acc[4][4];
#pragma unroll
    for (int i = 0; i < 4; i++) {
        m[i] = -1e30f;
        l[i] = 0.0f;
#pragma unroll
        for (int j = 0; j < 4; j++) acc[i][j] = 0.0f;
    }
    __syncthreads();

    for (int kt2 = 0; kt2 < NSEQ / 64; kt2++) {
        const float* kbase = qkv + ((size_t)(b * NSEQ + kt2 * 64)) * QKV_COLS + EMBED + h * DH;
        const float* vbase = qkv + ((size_t)(b * NSEQ + kt2 * 64)) * QKV_COLS + 2 * EMBED + h * DH;
        load_tile_T(Kt, kbase, QKV_COLS);
        load_tile_N(Vs, vbase, QKV_COLS);
        __syncthreads();

        // S = Q @ K^T (4x4 per thread), rank-1 over d
        float s[4][4];
#pragma unroll
        for (int i = 0; i < 4; i++)
#pragma unroll
            for (int j = 0; j < 4; j++) s[i][j] = 0.0f;

#pragma unroll 8
        for (int d = 0; d < DH; d++) {
            float4 a = *(const float4*)&Qt[d * AS + (ty << 2)];
            float4 kk = *(const float4*)&Kt[d * AS + (tx << 2)];
            float ar[4] = {a.x, a.y, a.z, a.w};
            float kr[4] = {kk.x, kk.y, kk.z, kk.w};
#pragma unroll
            for (int i = 0; i < 4; i++)
#pragma unroll
                for (int j = 0; j < 4; j++)
                    s[i][j] += ar[i] * kr[j];
        }

        // scale + row max over this tile
        float mt[4];
#pragma unroll
        for (int i = 0; i < 4; i++) {
            s[i][0] *= ATTN_SCALE; s[i][1] *= ATTN_SCALE;
            s[i][2] *= ATTN_SCALE; s[i][3] *= ATTN_SCALE;
            mt[i] = fmaxf(fmaxf(s[i][0], s[i][1]), fmaxf(s[i][2], s[i][3]));
        }
#pragma unroll
        for (int mask = 1; mask < 16; mask <<= 1)
#pragma unroll
            for (int i = 0; i < 4; i++)
                mt[i] = fmaxf(mt[i], __shfl_xor_sync(0xffffffffu, mt[i], mask));

        // online softmax update
        float corr[4], rs[4];
#pragma unroll
        for (int i = 0; i < 4; i++) {
            float mn = fmaxf(m[i], mt[i]);
            corr[i] = __expf(m[i] - mn);
            m[i] = mn;
            rs[i] = 0.0f;
#pragma unroll
            for (int j = 0; j < 4; j++) {
                float p = __expf(s[i][j] - mn);
                s[i][j] = p;
                rs[i] += p;
            }
#pragma unroll
            for (int j = 0; j < 4; j++) acc[i][j] *= corr[i];
        }
#pragma unroll
        for (int mask = 1; mask < 16; mask <<= 1)
#pragma unroll
            for (int i = 0; i < 4; i++)
                rs[i] += __shfl_xor_sync(0xffffffffu, rs[i], mask);
#pragma unroll
        for (int i = 0; i < 4; i++) l[i] = l[i] * corr[i] + rs[i];

        // stash P transposed: Pt[kc][q]
#pragma unroll
        for (int j = 0; j < 4; j++)
#pragma unroll
            for (int i = 0; i < 4; i++)
                Pt[((tx << 2) + j) * AS + (ty << 2) + i] = s[i][j];
        __syncthreads();

        // O += P @ V, rank-1 over kc
#pragma unroll 8
        for (int kc = 0; kc < 64; kc++) {
            float4 a = *(const float4*)&Pt[kc * AS + (ty << 2)];
            float4 v = *(const float4*)&Vs[kc * AS + (tx << 2)];
            float pr[4] = {a.x, a.y, a.z, a.w};
            float vr[4] = {v.x, v.y, v.z, v.w};
#pragma unroll
            for (int i = 0; i < 4; i++)
#pragma unroll
                for (int j = 0; j < 4; j++)
                    acc[i][j] += pr[i] * vr[j];
        }
        __syncthreads();
    }

    // epilogue: normalize and write to g_att[(b*N + q)*EMBED + h*64 + d]
#pragma unroll
    for (int i = 0; i < 4; i++) {
        float inv = 1.0f / l[i];
        int row = b * NSEQ + qt * 64 + (ty << 2) + i;
        float4 o;
        o.x = acc[i][0] * inv;
        o.y = acc[i][1] * inv;
        o.z = acc[i][2] * inv;
        o.w = acc[i][3] * inv;
        *(float4*)(out + (size_t)row * EMBED + h * DH + (tx << 2)) = o;
    }
}

// ---------------------------------------------------------------------------
extern "C" void kernel_launch(void* const* d_in, const int* in_sizes, int n_in,
                              void* d_out, int out_size)
{
    const float* x      = (const float*)d_in[0];
    const float* w_qkv  = (const float*)d_in[1];
    const float* b_qkv  = (const float*)d_in[2];
    const float* w_proj = (const float*)d_in[3];
    const float* b_proj = (const float*)d_in[4];
    float* out = (float*)d_out;

    float* qkv; cudaGetSymbolAddress((void**)&qkv, g_qkv);
    float* att; cudaGetSymbolAddress((void**)&att, g_att);

    cudaFuncSetAttribute(attn_kernel,
                         cudaFuncAttributeMaxDynamicSharedMemorySize,
                         4 * TILE_F * (int)sizeof(float));

    // 1) QKV projection: [4096,3072] = x[4096,1024] @ w_qkv[3072,1024]^T
    sgemm_bt<<<dim3(QKV_COLS / 128, ROWS / 128), 256>>>(
        x, w_qkv, b_qkv, qkv, ROWS, QKV_COLS, EMBED);

    // 2) Fused attention
    attn_kernel<<<dim3(BATCH * HEADS, NSEQ / 64), 256,
                  4 * TILE_F * sizeof(float)>>>(qkv, att);

    // 3) Output projection: [4096,1024] = att @ w_proj[1024,1024]^T
    sgemm_bt<<<dim3(EMBED / 128, ROWS / 128), 256>>>(
        att, w_proj, b_proj, out, ROWS, EMBED, EMBED);
}

// round 4
// speedup vs baseline: 1.2217x; 1.2217x over previous
#include <cuda_runtime.h>
#include <cuda_bf16.h>
#include <cstdint>

#define EMBED   1024
#define HEADS   16
#define DH      64
#define NSEQ    2048
#define BATCH   2
#define ROWS    (BATCH * NSEQ)          // 4096
#define QKV_COLS (3 * EMBED)            // 3072
#define K3      (3 * EMBED)             // split-expanded K = 3072
#define ATTN_SCALE 0.125f               // 64^-0.5

typedef __nv_bfloat16 bf16;

// ------------------------- scratch (__device__ globals) ---------------------
__device__ float g_qkv[(size_t)ROWS * QKV_COLS];    // 50.3 MB fp32
__device__ float g_att[(size_t)ROWS * EMBED];       // 16.8 MB fp32
__device__ bf16  g_x3 [(size_t)ROWS * K3];          // 25.2 MB  [Ah|Ah|Al]
__device__ bf16  g_wq3[(size_t)QKV_COLS * K3];      // 18.9 MB  [Bh|Bl|Bh]
__device__ bf16  g_at3[(size_t)ROWS * K3];          // 25.2 MB
__device__ bf16  g_wp3[(size_t)EMBED * K3];         // 6.3 MB

// ----------------------------- helpers --------------------------------------
__device__ __forceinline__ uint32_t smem_u32(const void* p) {
    uint32_t a;
    asm("{ .reg .u64 t; cvta.to.shared.u64 t, %1; cvt.u32.u64 %0, t; }"
        : "=r"(a) : "l"(p));
    return a;
}

__device__ __forceinline__ void cp16(uint32_t dst, const void* src) {
    asm volatile("cp.async.cg.shared.global [%0], [%1], 16;"
                 :: "r"(dst), "l"(src) : "memory");
}
#define CP_COMMIT() asm volatile("cp.async.commit_group;" ::: "memory")

__device__ __forceinline__ void mma16816(float* c, const uint32_t* a, const uint32_t* b) {
    asm volatile(
        "mma.sync.aligned.m16n8k16.row.col.f32.bf16.bf16.f32 "
        "{%0,%1,%2,%3}, {%4,%5,%6,%7}, {%8,%9}, {%0,%1,%2,%3};"
        : "+f"(c[0]), "+f"(c[1]), "+f"(c[2]), "+f"(c[3])
        : "r"(a[0]), "r"(a[1]), "r"(a[2]), "r"(a[3]), "r"(b[0]), "r"(b[1]));
}

// --------------------------- split conversion -------------------------------
// src: [R][1024] fp32 row-major. dst: [R][3072] bf16.
// btype=0 (activations): [hi | hi | lo]
// btype=1 (weights):     [hi | lo | hi]
// => A3 . B3^T = Ah Bh + Ah Bl + Al Bh  (drop lo*lo ~ 2^-32)
__global__ __launch_bounds__(256) void split3_kernel(
    const float* __restrict__ src, bf16* __restrict__ dst, int n4, int btype)
{
    int i = blockIdx.x * blockDim.x + threadIdx.x;
    if (i >= n4) return;
    int r = i >> 8;                 // 256 float4 per 1024-wide row
    int c = (i & 255) << 2;
    float4 v = ((const float4*)src)[i];
    bf16 h0 = __float2bfloat16_rn(v.x);
    bf16 h1 = __float2bfloat16_rn(v.y);
    bf16 h2 = __float2bfloat16_rn(v.z);
    bf16 h3 = __float2bfloat16_rn(v.w);
    bf16 l0 = __float2bfloat16_rn(v.x - __bfloat162float(h0));
    bf16 l1 = __float2bfloat16_rn(v.y - __bfloat162float(h1));
    bf16 l2 = __float2bfloat16_rn(v.z - __bfloat162float(h2));
    bf16 l3 = __float2bfloat16_rn(v.w - __bfloat162float(h3));
    __nv_bfloat162 hv0(h0, h1), hv1(h2, h3);
    __nv_bfloat162 lv0(l0, l1), lv1(l2, l3);

    bf16* base = dst + (size_t)r * K3 + c;
    // segment 0: hi
    *(__nv_bfloat162*)(base)     = hv0;
    *(__nv_bfloat162*)(base + 2) = hv1;
    if (btype) {    // weights: [hi | lo | hi]
        *(__nv_bfloat162*)(base + EMBED)         = lv0;
        *(__nv_bfloat162*)(base + EMBED + 2)     = lv1;
        *(__nv_bfloat162*)(base + 2 * EMBED)     = hv0;
        *(__nv_bfloat162*)(base + 2 * EMBED + 2) = hv1;
    } else {        // activations: [hi | hi | lo]
        *(__nv_bfloat162*)(base + EMBED)         = hv0;
        *(__nv_bfloat162*)(base + EMBED + 2)     = hv1;
        *(__nv_bfloat162*)(base + 2 * EMBED)     = lv0;
        *(__nv_bfloat162*)(base + 2 * EMBED + 2) = lv1;
    }
}

// ------------------------ bf16 HMMA GEMM (mma.sync) --------------------------
// C[M][N] = A3[M][K3] @ B3[N][K3]^T + bias[N], fp32 accumulate.
// CTA 128x128, BK=32, 256 threads = 8 warps (2M x 4N), warptile 64x32.
// Double-buffered cp.async smem; row stride 40 bf16 (80B): 16B-aligned chunks,
// conflict-free b32 fragment loads (banks (20r + c) mod 32 all distinct).
#define BM 128
#define BN 128
#define BK 32
#define SSTRIDE 40

__global__ __launch_bounds__(256) void gemm_mma(
    const bf16* __restrict__ A, const bf16* __restrict__ B,
    const float* __restrict__ bias, float* __restrict__ C, int M, int N)
{
    __shared__ __align__(16) bf16 As[2][BM][SSTRIDE];
    __shared__ __align__(16) bf16 Bs[2][BN][SSTRIDE];

    const int t    = threadIdx.x;
    const int lane = t & 31;
    const int wid  = t >> 5;
    const int wm   = wid >> 2;          // 0..1
    const int wn   = wid & 3;           // 0..3
    const int bm   = blockIdx.y << 7;
    const int bn   = blockIdx.x << 7;

    const bf16* Ab = A + (size_t)bm * K3;
    const bf16* Bb = B + (size_t)bn * K3;

    float acc[4][4][4];
#pragma unroll
    for (int mf = 0; mf < 4; mf++)
#pragma unroll
        for (int nf = 0; nf < 4; nf++)
#pragma unroll
            for (int q = 0; q < 4; q++) acc[mf][nf][q] = 0.0f;

    const int KT = K3 / BK;             // 96

    // tile loader: 512 16B-chunks per matrix, 2 per thread
    auto load_tile = [&](int kt, int s) {
#pragma unroll
        for (int j = 0; j < 2; j++) {
            int idx = (j << 8) + t;     // 0..511
            int r   = idx >> 2;         // 0..127
            int c   = idx & 3;          // 16B chunk in 64B row
            cp16(smem_u32(&As[s][r][c << 3]), Ab + (size_t)r * K3 + kt * BK + (c << 3));
            cp16(smem_u32(&Bs[s][r][c << 3]), Bb + (size_t)r * K3 + kt * BK + (c << 3));
        }
    };

    load_tile(0, 0);
    CP_COMMIT();

    for (int kt = 0; kt < KT; kt++) {
        if (kt + 1 < KT) {
            load_tile(kt + 1, (kt + 1) & 1);
            CP_COMMIT();
            asm volatile("cp.async.wait_group 1;" ::: "memory");
        } else {
            asm volatile("cp.async.wait_group 0;" ::: "memory");
        }
        __syncthreads();

        const int s = kt & 1;
#pragma unroll
        for (int ks = 0; ks < 2; ks++) {
            const int k0  = ks * 16 + ((lane & 3) << 1);
            const int row = lane >> 2;
            uint32_t a[4][4], b[4][2];
#pragma unroll
            for (int mf = 0; mf < 4; mf++) {
                int r0 = wm * 64 + mf * 16 + row;
                a[mf][0] = *(const uint32_t*)&As[s][r0][k0];
                a[mf][1] = *(const uint32_t*)&As[s][r0 + 8][k0];
                a[mf][2] = *(const uint32_t*)&As[s][r0][k0 + 8];
                a[mf][3] = *(const uint32_t*)&As[s][r0 + 8][k0 + 8];
            }
#pragma unroll
            for (int nf = 0; nf < 4; nf++) {
                int n0 = wn * 32 + nf * 8 + row;
                b[nf][0] = *(const uint32_t*)&Bs[s][n0][k0];
                b[nf][1] = *(const uint32_t*)&Bs[s][n0][k0 + 8];
            }
#pragma unroll
            for (int mf = 0; mf < 4; mf++)
#pragma unroll
                for (int nf = 0; nf < 4; nf++)
                    mma16816(acc[mf][nf], a[mf], b[nf]);
        }
        __syncthreads();
    }

    // epilogue: c0,c1 at (row, col..col+1); c2,c3 at (row+8, col..col+1)
#pragma unroll
    for (int mf = 0; mf < 4; mf++) {
#pragma unroll
        for (int nf = 0; nf < 4; nf++) {
            int r0 = bm + wm * 64 + mf * 16 + (lane >> 2);
            int c0 = bn + wn * 32 + nf * 8 + ((lane & 3) << 1);
            float2 bo = *(const float2*)(bias + c0);
            float2 o0, o1;
            o0.x = acc[mf][nf][0] + bo.x;
            o0.y = acc[mf][nf][1] + bo.y;
            o1.x = acc[mf][nf][2] + bo.x;
            o1.y = acc[mf][nf][3] + bo.y;
            *(float2*)(C + (size_t)r0 * N + c0)       = o0;
            *(float2*)(C + (size_t)(r0 + 8) * N + c0) = o1;
        }
    }
}

// ---------------------------------------------------------------------------
// Fused flash attention, fp32 (unchanged, verified in round 1)
// ---------------------------------------------------------------------------
#define AS 68
#define TILE_F (64 * AS)

__device__ __forceinline__ void load_tile_T(float* St, const float* g, int ldg) {
    int t = threadIdx.x;
#pragma unroll
    for (int i = 0; i < 4; i++) {
        int idx = (i << 8) + t;
        int r   = idx >> 4;
        int dv  = idx & 15;
        float4 v = *(const float4*)(g + (size_t)r * ldg + (dv << 2));
        St[(dv * 4 + 0) * AS + r] = v.x;
        St[(dv * 4 + 1) * AS + r] = v.y;
        St[(dv * 4 + 2) * AS + r] = v.z;
        St[(dv * 4 + 3) * AS + r] = v.w;
    }
}

__device__ __forceinline__ void load_tile_N(float* St, const float* g, int ldg) {
    int t = threadIdx.x;
#pragma unroll
    for (int i = 0; i < 4; i++) {
        int idx = (i << 8) + t;
        int r   = idx >> 4;
        int dv  = idx & 15;
        float4 v = *(const float4*)(g + (size_t)r * ldg + (dv << 2));
        *(float4*)&St[r * AS + (dv << 2)] = v;
    }
}

__global__ __launch_bounds__(256) void attn_kernel(
    const float* __restrict__ qkv, float* __restrict__ out)
{
    const int bh = blockIdx.x;
    const int b  = bh >> 4;
    const int h  = bh & 15;
    const int qt = blockIdx.y;

    extern __shared__ float sm[];
    float* Qt = sm;
    float* Kt = sm + TILE_F;
    float* Vs = sm + 2 * TILE_F;
    float* Pt = sm + 3 * TILE_F;

    const int t  = threadIdx.x;
    const int tx = t & 15;
    const int ty = t >> 4;

    const float* qbase = qkv + ((size_t)(b * NSEQ + qt * 64)) * QKV_COLS + h * DH;
    load_tile_T(Qt, qbase, QKV_COLS);

    float m[4], l[4], acc[4][4];
#pragma unroll
    for (int i = 0; i < 4; i++) {
        m[i] = -1e30f;
        l[i] = 0.0f;
#pragma unroll
        for (int j = 0; j < 4; j++) acc[i][j] = 0.0f;
    }
    __syncthreads();

    for (int kt2 = 0; kt2 < NSEQ / 64; kt2++) {
        const float* kbase = qkv + ((size_t)(b * NSEQ + kt2 * 64)) * QKV_COLS + EMBED + h * DH;
        const float* vbase = qkv + ((size_t)(b * NSEQ + kt2 * 64)) * QKV_COLS + 2 * EMBED + h * DH;
        load_tile_T(Kt, kbase, QKV_COLS);
        load_tile_N(Vs, vbase, QKV_COLS);
        __syncthreads();

        float s[4][4];
#pragma unroll
        for (int i = 0; i < 4; i++)
#pragma unroll
            for (int j = 0; j < 4; j++) s[i][j] = 0.0f;

#pragma unroll 8
        for (int d = 0; d < DH; d++) {
            float4 a  = *(const float4*)&Qt[d * AS + (ty << 2)];
            float4 kk = *(const float4*)&Kt[d * AS + (tx << 2)];
            float ar[4] = {a.x, a.y, a.z, a.w};
            float kr[4] = {kk.x, kk.y, kk.z, kk.w};
#pragma unroll
            for (int i = 0; i < 4; i++)
#pragma unroll
                for (int j = 0; j < 4; j++)
                    s[i][j] += ar[i] * kr[j];
        }

        float mt[4];
#pragma unroll
        for (int i = 0; i < 4; i++) {
            s[i][0] *= ATTN_SCALE; s[i][1] *= ATTN_SCALE;
            s[i][2] *= ATTN_SCALE; s[i][3] *= ATTN_SCALE;
            mt[i] = fmaxf(fmaxf(s[i][0], s[i][1]), fmaxf(s[i][2], s[i][3]));
        }
#pragma unroll
        for (int mask = 1; mask < 16; mask <<= 1)
#pragma unroll
            for (int i = 0; i < 4; i++)
                mt[i] = fmaxf(mt[i], __shfl_xor_sync(0xffffffffu, mt[i], mask));

        float corr[4], rs[4];
#pragma unroll
        for (int i = 0; i < 4; i++) {
            float mn = fmaxf(m[i], mt[i]);
            corr[i] = __expf(m[i] - mn);
            m[i] = mn;
            rs[i] = 0.0f;
#pragma unroll
            for (int j = 0; j < 4; j++) {
                float p = __expf(s[i][j] - mn);
                s[i][j] = p;
                rs[i] += p;
            }
#pragma unroll
            for (int j = 0; j < 4; j++) acc[i][j] *= corr[i];
        }
#pragma unroll
        for (int mask = 1; mask < 16; mask <<= 1)
#pragma unroll
            for (int i = 0; i < 4; i++)
                rs[i] += __shfl_xor_sync(0xffffffffu, rs[i], mask);
#pragma unroll
        for (int i = 0; i < 4; i++) l[i] = l[i] * corr[i] + rs[i];

#pragma unroll
        for (int j = 0; j < 4; j++)
#pragma unroll
            for (int i = 0; i < 4; i++)
                Pt[((tx << 2) + j) * AS + (ty << 2) + i] = s[i][j];
        __syncthreads();

#pragma unroll 8
        for (int kc = 0; kc < 64; kc++) {
            float4 a = *(const float4*)&Pt[kc * AS + (ty << 2)];
            float4 v = *(const float4*)&Vs[kc * AS + (tx << 2)];
            float pr[4] = {a.x, a.y, a.z, a.w};
            float vr[4] = {v.x, v.y, v.z, v.w};
#pragma unroll
            for (int i = 0; i < 4; i++)
#pragma unroll
                for (int j = 0; j < 4; j++)
                    acc[i][j] += pr[i] * vr[j];
        }
        __syncthreads();
    }

#pragma unroll
    for (int i = 0; i < 4; i++) {
        float inv = 1.0f / l[i];
        int row = b * NSEQ + qt * 64 + (ty << 2) + i;
        float4 o;
        o.x = acc[i][0] * inv;
        o.y = acc[i][1] * inv;
        o.z = acc[i][2] * inv;
        o.w = acc[i][3] * inv;
        *(float4*)(out + (size_t)row * EMBED + h * DH + (tx << 2)) = o;
    }
}

// ---------------------------------------------------------------------------
extern "C" void kernel_launch(void* const* d_in, const int* in_sizes, int n_in,
                              void* d_out, int out_size)
{
    const float* x      = (const float*)d_in[0];
    const float* w_qkv  = (const float*)d_in[1];
    const float* b_qkv  = (const float*)d_in[2];
    const float* w_proj = (const float*)d_in[3];
    const float* b_proj = (const float*)d_in[4];
    float* out = (float*)d_out;

    float* qkv; cudaGetSymbolAddress((void**)&qkv, g_qkv);
    float* att; cudaGetSymbolAddress((void**)&att, g_att);
    bf16 *x3, *wq3, *at3, *wp3;
    cudaGetSymbolAddress((void**)&x3,  g_x3);
    cudaGetSymbolAddress((void**)&wq3, g_wq3);
    cudaGetSymbolAddress((void**)&at3, g_at3);
    cudaGetSymbolAddress((void**)&wp3, g_wp3);

    cudaFuncSetAttribute(attn_kernel,
                         cudaFuncAttributeMaxDynamicSharedMemorySize,
                         4 * TILE_F * (int)sizeof(float));

    // split inputs for QKV GEMM
    {
        int n4 = ROWS * EMBED / 4;
        split3_kernel<<<(n4 + 255) / 256, 256>>>(x, x3, n4, 0);
        int m4 = QKV_COLS * EMBED / 4;
        split3_kernel<<<(m4 + 255) / 256, 256>>>(w_qkv, wq3, m4, 1);
    }

    // 1) QKV projection: [4096,3072] = x3 @ wq3^T + b
    gemm_mma<<<dim3(QKV_COLS / 128, ROWS / 128), 256>>>(
        x3, wq3, b_qkv, qkv, ROWS, QKV_COLS);

    // 2) fused attention (fp32)
    attn_kernel<<<dim3(BATCH * HEADS, NSEQ / 64), 256,
                  4 * TILE_F * sizeof(float)>>>(qkv, att);

    // split inputs for proj GEMM
    {
        int n4 = ROWS * EMBED / 4;
        split3_kernel<<<(n4 + 255) / 256, 256>>>(att, at3, n4, 0);
        int m4 = EMBED * EMBED / 4;
        split3_kernel<<<(m4 + 255) / 256, 256>>>(w_proj, wp3, m4, 1);
    }

    // 3) output projection: [4096,1024] = at3 @ wp3^T + b
    gemm_mma<<<dim3(EMBED / 128, ROWS / 128), 256>>>(
        at3, wp3, b_proj, out, ROWS, EMBED);
}

// round 6
// speedup vs baseline: 1.3144x; 1.0759x over previous
#include <cuda_runtime.h>
#include <cuda_bf16.h>
#include <cstdint>

#define EMBED   1024
#define HEADS   16
#define DH      64
#define NSEQ    2048
#define BATCH   2
#define ROWS    (BATCH * NSEQ)          // 4096
#define QKV_COLS (3 * EMBED)            // 3072
#define K3      (3 * EMBED)             // split-expanded K = 3072
#define ATTN_SCALE 0.125f               // 64^-0.5

typedef __nv_bfloat16 bf16;

// ------------------------- scratch (__device__ globals) ---------------------
__device__ float g_qkv[(size_t)ROWS * QKV_COLS];    // 50.3 MB fp32
__device__ float g_att[(size_t)ROWS * EMBED];       // 16.8 MB fp32
__device__ bf16  g_x3 [(size_t)ROWS * K3];          // 25.2 MB  [Ah|Ah|Al]
__device__ bf16  g_wq3[(size_t)QKV_COLS * K3];      // 18.9 MB  [Bh|Bl|Bh]
__device__ bf16  g_at3[(size_t)ROWS * K3];          // 25.2 MB
__device__ bf16  g_wp3[(size_t)EMBED * K3];         // 6.3 MB

// ----------------------------- helpers --------------------------------------
__device__ __forceinline__ uint32_t smem_u32(const void* p) {
    uint32_t a;
    asm("{ .reg .u64 t; cvta.to.shared.u64 t, %1; cvt.u32.u64 %0, t; }"
        : "=r"(a) : "l"(p));
    return a;
}

__device__ __forceinline__ void cp16(uint32_t dst, const void* src) {
    asm volatile("cp.async.cg.shared.global [%0], [%1], 16;"
                 :: "r"(dst), "l"(src) : "memory");
}
#define CP_COMMIT() asm volatile("cp.async.commit_group;" ::: "memory")

__device__ __forceinline__ void mma16816(float* c, const uint32_t* a, const uint32_t* b) {
    asm volatile(
        "mma.sync.aligned.m16n8k16.row.col.f32.bf16.bf16.f32 "
        "{%0,%1,%2,%3}, {%4,%5,%6,%7}, {%8,%9}, {%0,%1,%2,%3};"
        : "+f"(c[0]), "+f"(c[1]), "+f"(c[2]), "+f"(c[3])
        : "r"(a[0]), "r"(a[1]), "r"(a[2]), "r"(a[3]), "r"(b[0]), "r"(b[1]));
}

// --------------------------- split conversion -------------------------------
// src: [R][1024] fp32 row-major. dst: [R][3072] bf16.
// btype=0 (activations): [hi | hi | lo]
// btype=1 (weights):     [hi | lo | hi]
// => A3 . B3^T = Ah Bh + Ah Bl + Al Bh  (drop lo*lo ~ 2^-32)
__global__ __launch_bounds__(256) void split3_kernel(
    const float* __restrict__ src, bf16* __restrict__ dst, int n4, int btype)
{
    int i = blockIdx.x * blockDim.x + threadIdx.x;
    if (i >= n4) return;
    int r = i >> 8;                 // 256 float4 per 1024-wide row
    int c = (i & 255) << 2;
    float4 v = ((const float4*)src)[i];
    bf16 h0 = __float2bfloat16_rn(v.x);
    bf16 h1 = __float2bfloat16_rn(v.y);
    bf16 h2 = __float2bfloat16_rn(v.z);
    bf16 h3 = __float2bfloat16_rn(v.w);
    bf16 l0 = __float2bfloat16_rn(v.x - __bfloat162float(h0));
    bf16 l1 = __float2bfloat16_rn(v.y - __bfloat162float(h1));
    bf16 l2 = __float2bfloat16_rn(v.z - __bfloat162float(h2));
    bf16 l3 = __float2bfloat16_rn(v.w - __bfloat162float(h3));
    __nv_bfloat162 hv0(h0, h1), hv1(h2, h3);
    __nv_bfloat162 lv0(l0, l1), lv1(l2, l3);

    bf16* base = dst + (size_t)r * K3 + c;
    *(__nv_bfloat162*)(base)     = hv0;
    *(__nv_bfloat162*)(base + 2) = hv1;
    if (btype) {    // weights: [hi | lo | hi]
        *(__nv_bfloat162*)(base + EMBED)         = lv0;
        *(__nv_bfloat162*)(base + EMBED + 2)     = lv1;
        *(__nv_bfloat162*)(base + 2 * EMBED)     = hv0;
        *(__nv_bfloat162*)(base + 2 * EMBED + 2) = hv1;
    } else {        // activations: [hi | hi | lo]
        *(__nv_bfloat162*)(base + EMBED)         = hv0;
        *(__nv_bfloat162*)(base + EMBED + 2)     = hv1;
        *(__nv_bfloat162*)(base + 2 * EMBED)     = lv0;
        *(__nv_bfloat162*)(base + 2 * EMBED + 2) = lv1;
    }
}

// ------------------------ bf16 HMMA GEMM (mma.sync) --------------------------
#define BM 128
#define BN 128
#define BK 32
#define SSTRIDE 40

__global__ __launch_bounds__(256) void gemm_mma(
    const bf16* __restrict__ A, const bf16* __restrict__ B,
    const float* __restrict__ bias, float* __restrict__ C, int M, int N)
{
    __shared__ __align__(16) bf16 As[2][BM][SSTRIDE];
    __shared__ __align__(16) bf16 Bs[2][BN][SSTRIDE];

    const int t    = threadIdx.x;
    const int lane = t & 31;
    const int wid  = t >> 5;
    const int wm   = wid >> 2;          // 0..1
    const int wn   = wid & 3;           // 0..3
    const int bm   = blockIdx.y << 7;
    const int bn   = blockIdx.x << 7;

    const bf16* Ab = A + (size_t)bm * K3;
    const bf16* Bb = B + (size_t)bn * K3;

    float acc[4][4][4];
#pragma unroll
    for (int mf = 0; mf < 4; mf++)
#pragma unroll
        for (int nf = 0; nf < 4; nf++)
#pragma unroll
            for (int q = 0; q < 4; q++) acc[mf][nf][q] = 0.0f;

    const int KT = K3 / BK;             // 96

    auto load_tile = [&](int kt, int s) {
#pragma unroll
        for (int j = 0; j < 2; j++) {
            int idx = (j << 8) + t;     // 0..511
            int r   = idx >> 2;         // 0..127
            int c   = idx & 3;          // 16B chunk in 64B row
            cp16(smem_u32(&As[s][r][c << 3]), Ab + (size_t)r * K3 + kt * BK + (c << 3));
            cp16(smem_u32(&Bs[s][r][c << 3]), Bb + (size_t)r * K3 + kt * BK + (c << 3));
        }
    };

    load_tile(0, 0);
    CP_COMMIT();

    for (int kt = 0; kt < KT; kt++) {
        if (kt + 1 < KT) {
            load_tile(kt + 1, (kt + 1) & 1);
            CP_COMMIT();
            asm volatile("cp.async.wait_group 1;" ::: "memory");
        } else {
            asm volatile("cp.async.wait_group 0;" ::: "memory");
        }
        __syncthreads();

        const int s = kt & 1;
#pragma unroll
        for (int ks = 0; ks < 2; ks++) {
            const int k0  = ks * 16 + ((lane & 3) << 1);
            const int row = lane >> 2;
            uint32_t a[4][4], b[4][2];
#pragma unroll
            for (int mf = 0; mf < 4; mf++) {
                int r0 = wm * 64 + mf * 16 + row;
                a[mf][0] = *(const uint32_t*)&As[s][r0][k0];
                a[mf][1] = *(const uint32_t*)&As[s][r0 + 8][k0];
                a[mf][2] = *(const uint32_t*)&As[s][r0][k0 + 8];
                a[mf][3] = *(const uint32_t*)&As[s][r0 + 8][k0 + 8];
            }
#pragma unroll
            for (int nf = 0; nf < 4; nf++) {
                int n0 = wn * 32 + nf * 8 + row;
                b[nf][0] = *(const uint32_t*)&Bs[s][n0][k0];
                b[nf][1] = *(const uint32_t*)&Bs[s][n0][k0 + 8];
            }
#pragma unroll
            for (int mf = 0; mf < 4; mf++)
#pragma unroll
                for (int nf = 0; nf < 4; nf++)
                    mma16816(acc[mf][nf], a[mf], b[nf]);
        }
        __syncthreads();
    }

#pragma unroll
    for (int mf = 0; mf < 4; mf++) {
#pragma unroll
        for (int nf = 0; nf < 4; nf++) {
            int r0 = bm + wm * 64 + mf * 16 + (lane >> 2);
            int c0 = bn + wn * 32 + nf * 8 + ((lane & 3) << 1);
            float2 bo = *(const float2*)(bias + c0);
            float2 o0, o1;
            o0.x = acc[mf][nf][0] + bo.x;
            o0.y = acc[mf][nf][1] + bo.y;
            o1.x = acc[mf][nf][2] + bo.x;
            o1.y = acc[mf][nf][3] + bo.y;
            *(float2*)(C + (size_t)r0 * N + c0)       = o0;
            *(float2*)(C + (size_t)(r0 + 8) * N + c0) = o1;
        }
    }
}

// ---------------------------------------------------------------------------
// Fused flash attention, fp32, WIDE tiles: 128q x 128k per CTA, 256 threads,
// 8x8 per-thread QK tile (1.0 B/FFMA), 8x4 PV tile. Online softmax.
// Smem: Qt[64][AS2] Kt[64][AS2] (d-major), Vs[128][VS2], Pt[128][AS2] (k-major).
// ---------------------------------------------------------------------------
#define AS2 132
#define VS2 68
#define ATT_SMEM_FLOATS (64 * AS2 * 2 + 128 * VS2 + 128 * AS2)

// 128 rows x 64 cols, transposed into St[d][r], stride AS2
__device__ __forceinline__ void load_T128(float* St, const float* g, int ldg) {
    int t = threadIdx.x;
#pragma unroll
    for (int i = 0; i < 8; i++) {
        int idx = (i << 8) + t;
        int r   = idx >> 4;     // 0..127
        int dv  = idx & 15;     // float4 index along d
        float4 v = *(const float4*)(g + (size_t)r * ldg + (dv << 2));
        St[(dv * 4 + 0) * AS2 + r] = v.x;
        St[(dv * 4 + 1) * AS2 + r] = v.y;
        St[(dv * 4 + 2) * AS2 + r] = v.z;
        St[(dv * 4 + 3) * AS2 + r] = v.w;
    }
}

// 128 rows x 64 cols, natural St[r][d], stride VS2
__device__ __forceinline__ void load_N128(float* St, const float* g, int ldg) {
    int t = threadIdx.x;
#pragma unroll
    for (int i = 0; i < 8; i++) {
        int idx = (i << 8) + t;
        int r   = idx >> 4;
        int dv  = idx & 15;
        float4 v = *(const float4*)(g + (size_t)r * ldg + (dv << 2));
        *(float4*)&St[r * VS2 + (dv << 2)] = v;
    }
}

__global__ __launch_bounds__(256) void attn_kernel(
    const float* __restrict__ qkv, float* __restrict__ out)
{
    const int bh = blockIdx.x;          // 0..31
    const int b  = bh >> 4;
    const int h  = bh & 15;
    const int qt = blockIdx.y;          // 0..15  (128-query tiles)

    extern __shared__ float sm[];
    float* Qt = sm;                         // [64][AS2]
    float* Kt = sm + 64 * AS2;              // [64][AS2]
    float* Vs = sm + 2 * 64 * AS2;          // [128][VS2]
    float* Pt = sm + 2 * 64 * AS2 + 128 * VS2;  // [128][AS2] (k-major)

    const int t  = threadIdx.x;
    const int tx = t & 15;              // key/dim columns
    const int ty = t >> 4;              // query rows

    const float* qbase = qkv + ((size_t)(b * NSEQ + qt * 128)) * QKV_COLS + h * DH;
    load_T128(Qt, qbase, QKV_COLS);

    float m[8], l[8], acc[8][4];
#pragma unroll
    for (int i = 0; i < 8; i++) {
        m[i] = -1e30f;
        l[i] = 0.0f;
#pragma unroll
        for (int j = 0; j < 4; j++) acc[i][j] = 0.0f;
    }

    for (int kt2 = 0; kt2 < NSEQ / 128; kt2++) {
        __syncthreads();   // prior iteration's PV reads done before overwrite
        const float* kbase = qkv + ((size_t)(b * NSEQ + kt2 * 128)) * QKV_COLS + EMBED + h * DH;
        const float* vbase = qkv + ((size_t)(b * NSEQ + kt2 * 128)) * QKV_COLS + 2 * EMBED + h * DH;
        load_T128(Kt, kbase, QKV_COLS);
        load_N128(Vs, vbase, QKV_COLS);
        __syncthreads();

        // ---- S = Q @ K^T : 8x8 per thread, rank-1 over d ----
        float s[8][8];
#pragma unroll
        for (int i = 0; i < 8; i++)
#pragma unroll
            for (int j = 0; j < 8; j++) s[i][j] = 0.0f;

#pragma unroll 4
        for (int d = 0; d < DH; d++) {
            float4 a0 = *(const float4*)&Qt[d * AS2 + (ty << 2)];
            float4 a1 = *(const float4*)&Qt[d * AS2 + 64 + (ty << 2)];
            float4 b0 = *(const float4*)&Kt[d * AS2 + (tx << 2)];
            float4 b1 = *(const float4*)&Kt[d * AS2 + 64 + (tx << 2)];
            float ar[8] = {a0.x, a0.y, a0.z, a0.w, a1.x, a1.y, a1.z, a1.w};
            float br[8] = {b0.x, b0.y, b0.z, b0.w, b1.x, b1.y, b1.z, b1.w};
#pragma unroll
            for (int i = 0; i < 8; i++)
#pragma unroll
                for (int j = 0; j < 8; j++)
                    s[i][j] += ar[i] * br[j];
        }

        // ---- scale + tile row max ----
        float mt[8];
#pragma unroll
        for (int i = 0; i < 8; i++) {
            float mx = -1e30f;
#pragma unroll
            for (int j = 0; j < 8; j++) {
                s[i][j] *= ATTN_SCALE;
                mx = fmaxf(mx, s[i][j]);
            }
            mt[i] = mx;
        }
#pragma unroll
        for (int mask = 1; mask < 16; mask <<= 1)
#pragma unroll
            for (int i = 0; i < 8; i++)
                mt[i] = fmaxf(mt[i], __shfl_xor_sync(0xffffffffu, mt[i], mask));

        // ---- online softmax update ----
        float corr[8], rs[8];
#pragma unroll
        for (int i = 0; i < 8; i++) {
            float mn = fmaxf(m[i], mt[i]);
            corr[i] = __expf(m[i] - mn);
            m[i] = mn;
            float r = 0.0f;
#pragma unroll
            for (int j = 0; j < 8; j++) {
                float p = __expf(s[i][j] - mn);
                s[i][j] = p;
                r += p;
            }
            rs[i] = r;
#pragma unroll
            for (int j = 0; j < 4; j++) acc[i][j] *= corr[i];
        }
#pragma unroll
        for (int mask = 1; mask < 16; mask <<= 1)
#pragma unroll
            for (int i = 0; i < 8; i++)
                rs[i] += __shfl_xor_sync(0xffffffffu, rs[i], mask);
#pragma unroll
        for (int i = 0; i < 8; i++) l[i] = l[i] * corr[i] + rs[i];

        // ---- stash P transposed: Pt[k][q], float4 over row groups ----
#pragma unroll
        for (int j = 0; j < 8; j++) {
            int col = (j < 4) ? ((tx << 2) + j) : (64 + (tx << 2) + (j - 4));
            float4 p0 = make_float4(s[0][j], s[1][j], s[2][j], s[3][j]);
            float4 p1 = make_float4(s[4][j], s[5][j], s[6][j], s[7][j]);
            *(float4*)&Pt[col * AS2 + (ty << 2)]      = p0;
            *(float4*)&Pt[col * AS2 + 64 + (ty << 2)] = p1;
        }
        __syncthreads();

        // ---- O += P @ V : 8x4 per thread, rank-1 over kc ----
#pragma unroll 4
        for (int kc = 0; kc < 128; kc++) {
            float4 a0 = *(const float4*)&Pt[kc * AS2 + (ty << 2)];
            float4 a1 = *(const float4*)&Pt[kc * AS2 + 64 + (ty << 2)];
            float4 v  = *(const float4*)&Vs[kc * VS2 + (tx << 2)];
            float pr[8] = {a0.x, a0.y, a0.z, a0.w, a1.x, a1.y, a1.z, a1.w};
            float vr[4] = {v.x, v.y, v.z, v.w};
#pragma unroll
            for (int i = 0; i < 8; i++)
#pragma unroll
                for (int j = 0; j < 4; j++)
                    acc[i][j] += pr[i] * vr[j];
        }
    }

    // ---- epilogue ----
#pragma unroll
    for (int i = 0; i < 8; i++) {
        float inv = 1.0f / l[i];
        int qrow = (i < 4) ? ((ty << 2) + i) : (64 + (ty << 2) + (i - 4));
        int row = b * NSEQ + qt * 128 + qrow;
        float4 o;
        o.x = acc[i][0] * inv;
        o.y = acc[i][1] * inv;
        o.z = acc[i][2] * inv;
        o.w = acc[i][3] * inv;
        *(float4*)(out + (size_t)row * EMBED + h * DH + (tx << 2)) = o;
    }
}

// ---------------------------------------------------------------------------
extern "C" void kernel_launch(void* const* d_in, const int* in_sizes, int n_in,
                              void* d_out, int out_size)
{
    const float* x      = (const float*)d_in[0];
    const float* w_qkv  = (const float*)d_in[1];
    const float* b_qkv  = (const float*)d_in[2];
    const float* w_proj = (const float*)d_in[3];
    const float* b_proj = (const float*)d_in[4];
    float* out = (float*)d_out;

    float* qkv; cudaGetSymbolAddress((void**)&qkv, g_qkv);
    float* att; cudaGetSymbolAddress((void**)&att, g_att);
    bf16 *x3, *wq3, *at3, *wp3;
    cudaGetSymbolAddress((void**)&x3,  g_x3);
    cudaGetSymbolAddress((void**)&wq3, g_wq3);
    cudaGetSymbolAddress((void**)&at3, g_at3);
    cudaGetSymbolAddress((void**)&wp3, g_wp3);

    cudaFuncSetAttribute(attn_kernel,
                         cudaFuncAttributeMaxDynamicSharedMemorySize,
                         ATT_SMEM_FLOATS * (int)sizeof(float));

    // split inputs for QKV GEMM
    {
        int n4 = ROWS * EMBED / 4;
        split3_kernel<<<(n4 + 255) / 256, 256>>>(x, x3, n4, 0);
        int m4 = QKV_COLS * EMBED / 4;
        split3_kernel<<<(m4 + 255) / 256, 256>>>(w_qkv, wq3, m4, 1);
    }

    // 1) QKV projection: [4096,3072] = x3 @ wq3^T + b
    gemm_mma<<<dim3(QKV_COLS / 128, ROWS / 128), 256>>>(
        x3, wq3, b_qkv, qkv, ROWS, QKV_COLS);

    // 2) fused attention (fp32, wide tiles)
    attn_kernel<<<dim3(BATCH * HEADS, NSEQ / 128), 256,
                  ATT_SMEM_FLOATS * sizeof(float)>>>(qkv, att);

    // split inputs for proj GEMM
    {
        int n4 = ROWS * EMBED / 4;
        split3_kernel<<<(n4 + 255) / 256, 256>>>(att, at3, n4, 0);
        int m4 = EMBED * EMBED / 4;
        split3_kernel<<<(m4 + 255) / 256, 256>>>(w_proj, wp3, m4, 1);
    }

    // 3) output projection: [4096,1024] = at3 @ wp3^T + b
    gemm_mma<<<dim3(EMBED / 128, ROWS / 128), 256>>>(
        at3, wp3, b_proj, out, ROWS, EMBED);
}

// round 7
// speedup vs baseline: 2.2036x; 1.6764x over previous
#include <cuda_runtime.h>
#include <cuda_bf16.h>
#include <cstdint>

#define EMBED   1024
#define HEADS   16
#define DH      64
#define NSEQ    2048
#define BATCH   2
#define ROWS    (BATCH * NSEQ)          // 4096
#define QKV_COLS (3 * EMBED)            // 3072
#define K3      (3 * EMBED)             // split-expanded K = 3072
#define ATTN_SCALE 0.125f               // 64^-0.5

typedef __nv_bfloat16 bf16;

// ------------------------- scratch (__device__ globals) ---------------------
__device__ float g_qkv[(size_t)ROWS * QKV_COLS];    // 50.3 MB fp32
__device__ float g_att[(size_t)ROWS * EMBED];       // 16.8 MB fp32
__device__ bf16  g_x3 [(size_t)ROWS * K3];          // [Ah|Ah|Al]
__device__ bf16  g_wq3[(size_t)QKV_COLS * K3];      // [Bh|Bl|Bh]
__device__ bf16  g_at3[(size_t)ROWS * K3];
__device__ bf16  g_wp3[(size_t)EMBED * K3];
// head-major split Q/K/V for HMMA attention: [bh][n][64]
__device__ bf16  g_qh[(size_t)ROWS * EMBED];
__device__ bf16  g_ql[(size_t)ROWS * EMBED];
__device__ bf16  g_kh[(size_t)ROWS * EMBED];
__device__ bf16  g_kl[(size_t)ROWS * EMBED];
__device__ bf16  g_vh[(size_t)ROWS * EMBED];
__device__ bf16  g_vl[(size_t)ROWS * EMBED];

// ----------------------------- helpers --------------------------------------
__device__ __forceinline__ uint32_t smem_u32(const void* p) {
    uint32_t a;
    asm("{ .reg .u64 t; cvta.to.shared.u64 t, %1; cvt.u32.u64 %0, t; }"
        : "=r"(a) : "l"(p));
    return a;
}

__device__ __forceinline__ void cp16(uint32_t dst, const void* src) {
    asm volatile("cp.async.cg.shared.global [%0], [%1], 16;"
                 :: "r"(dst), "l"(src) : "memory");
}
#define CP_COMMIT() asm volatile("cp.async.commit_group;" ::: "memory")

__device__ __forceinline__ void mma16816(float* c, const uint32_t* a, const uint32_t* b) {
    asm volatile(
        "mma.sync.aligned.m16n8k16.row.col.f32.bf16.bf16.f32 "
        "{%0,%1,%2,%3}, {%4,%5,%6,%7}, {%8,%9}, {%0,%1,%2,%3};"
        : "+f"(c[0]), "+f"(c[1]), "+f"(c[2]), "+f"(c[3])
        : "r"(a[0]), "r"(a[1]), "r"(a[2]), "r"(a[3]), "r"(b[0]), "r"(b[1]));
}

__device__ __forceinline__ void ldsm_x4_t(uint32_t& r0, uint32_t& r1,
                                          uint32_t& r2, uint32_t& r3, uint32_t addr) {
    asm volatile("ldmatrix.sync.aligned.m8n8.x4.trans.shared.b16 {%0,%1,%2,%3}, [%4];"
                 : "=r"(r0), "=r"(r1), "=r"(r2), "=r"(r3) : "r"(addr));
}

// pack two floats to bf16x2, return residuals
__device__ __forceinline__ uint32_t pack_split(float x, float y, float& rx, float& ry) {
    __nv_bfloat162 h = __float22bfloat162_rn(make_float2(x, y));
    float2 back = __bfloat1622float2(h);
    rx = x - back.x; ry = y - back.y;
    return *(uint32_t*)&h;
}
__device__ __forceinline__ uint32_t pack_only(float x, float y) {
    __nv_bfloat162 h = __float22bfloat162_rn(make_float2(x, y));
    return *(uint32_t*)&h;
}

// --------------------------- split conversions -------------------------------
// GEMM inputs: src [R][1024] fp32 -> dst [R][3072] bf16 (hi/lo segments)
__global__ __launch_bounds__(256) void split3_kernel(
    const float* __restrict__ src, bf16* __restrict__ dst, int n4, int btype)
{
    int i = blockIdx.x * blockDim.x + threadIdx.x;
    if (i >= n4) return;
    int r = i >> 8;
    int c = (i & 255) << 2;
    float4 v = ((const float4*)src)[i];
    bf16 h0 = __float2bfloat16_rn(v.x);
    bf16 h1 = __float2bfloat16_rn(v.y);
    bf16 h2 = __float2bfloat16_rn(v.z);
    bf16 h3 = __float2bfloat16_rn(v.w);
    bf16 l0 = __float2bfloat16_rn(v.x - __bfloat162float(h0));
    bf16 l1 = __float2bfloat16_rn(v.y - __bfloat162float(h1));
    bf16 l2 = __float2bfloat16_rn(v.z - __bfloat162float(h2));
    bf16 l3 = __float2bfloat16_rn(v.w - __bfloat162float(h3));
    __nv_bfloat162 hv0(h0, h1), hv1(h2, h3);
    __nv_bfloat162 lv0(l0, l1), lv1(l2, l3);

    bf16* base = dst + (size_t)r * K3 + c;
    *(__nv_bfloat162*)(base)     = hv0;
    *(__nv_bfloat162*)(base + 2) = hv1;
    if (btype) {
        *(__nv_bfloat162*)(base + EMBED)         = lv0;
        *(__nv_bfloat162*)(base + EMBED + 2)     = lv1;
        *(__nv_bfloat162*)(base + 2 * EMBED)     = hv0;
        *(__nv_bfloat162*)(base + 2 * EMBED + 2) = hv1;
    } else {
        *(__nv_bfloat162*)(base + EMBED)         = hv0;
        *(__nv_bfloat162*)(base + EMBED + 2)     = hv1;
        *(__nv_bfloat162*)(base + 2 * EMBED)     = lv0;
        *(__nv_bfloat162*)(base + 2 * EMBED + 2) = lv1;
    }
}

// qkv fp32 [row][3072] -> head-major split [bh][n][64] hi/lo for one segment
__global__ __launch_bounds__(256) void split_qkv(
    const float* __restrict__ qkv, bf16* __restrict__ dh, bf16* __restrict__ dl, int seg)
{
    int i = blockIdx.x * blockDim.x + threadIdx.x;  // over ROWS*1024/4
    if (i >= ROWS * EMBED / 4) return;
    int row = i >> 8;                 // token row (0..4095)
    int c   = (i & 255) << 2;         // col within 1024
    int h = c >> 6, d = c & 63;
    int b = row >> 11, n = row & 2047;
    float4 v = *(const float4*)(qkv + (size_t)row * QKV_COLS + seg * EMBED + c);
    bf16 h0 = __float2bfloat16_rn(v.x);
    bf16 h1 = __float2bfloat16_rn(v.y);
    bf16 h2 = __float2bfloat16_rn(v.z);
    bf16 h3 = __float2bfloat16_rn(v.w);
    bf16 l0 = __float2bfloat16_rn(v.x - __bfloat162float(h0));
    bf16 l1 = __float2bfloat16_rn(v.y - __bfloat162float(h1));
    bf16 l2 = __float2bfloat16_rn(v.z - __bfloat162float(h2));
    bf16 l3 = __float2bfloat16_rn(v.w - __bfloat162float(h3));
    size_t idx = (((size_t)(b * HEADS + h) * NSEQ) + n) * DH + d;
    *(__nv_bfloat162*)(dh + idx)     = __nv_bfloat162(h0, h1);
    *(__nv_bfloat162*)(dh + idx + 2) = __nv_bfloat162(h2, h3);
    *(__nv_bfloat162*)(dl + idx)     = __nv_bfloat162(l0, l1);
    *(__nv_bfloat162*)(dl + idx + 2) = __nv_bfloat162(l2, l3);
}

// ------------------------ bf16 HMMA GEMM (mma.sync) --------------------------
#define BM 128
#define BN 128
#define BK 32
#define SSTRIDE 40

__global__ __launch_bounds__(256) void gemm_mma(
    const bf16* __restrict__ A, const bf16* __restrict__ B,
    const float* __restrict__ bias, float* __restrict__ C, int M, int N)
{
    __shared__ __align__(16) bf16 As[2][BM][SSTRIDE];
    __shared__ __align__(16) bf16 Bs[2][BN][SSTRIDE];

    const int t    = threadIdx.x;
    const int lane = t & 31;
    const int wid  = t >> 5;
    const int wm   = wid >> 2;
    const int wn   = wid & 3;
    const int bm   = blockIdx.y << 7;
    const int bn   = blockIdx.x << 7;

    const bf16* Ab = A + (size_t)bm * K3;
    const bf16* Bb = B + (size_t)bn * K3;

    float acc[4][4][4];
#pragma unroll
    for (int mf = 0; mf < 4; mf++)
#pragma unroll
        for (int nf = 0; nf < 4; nf++)
#pragma unroll
            for (int q = 0; q < 4; q++) acc[mf][nf][q] = 0.0f;

    const int KT = K3 / BK;

    auto load_tile = [&](int kt, int s) {
#pragma unroll
        for (int j = 0; j < 2; j++) {
            int idx = (j << 8) + t;
            int r   = idx >> 2;
            int c   = idx & 3;
            cp16(smem_u32(&As[s][r][c << 3]), Ab + (size_t)r * K3 + kt * BK + (c << 3));
            cp16(smem_u32(&Bs[s][r][c << 3]), Bb + (size_t)r * K3 + kt * BK + (c << 3));
        }
    };

    load_tile(0, 0);
    CP_COMMIT();

    for (int kt = 0; kt < KT; kt++) {
        if (kt + 1 < KT) {
            load_tile(kt + 1, (kt + 1) & 1);
            CP_COMMIT();
            asm volatile("cp.async.wait_group 1;" ::: "memory");
        } else {
            asm volatile("cp.async.wait_group 0;" ::: "memory");
        }
        __syncthreads();

        const int s = kt & 1;
#pragma unroll
        for (int ks = 0; ks < 2; ks++) {
            const int k0  = ks * 16 + ((lane & 3) << 1);
            const int row = lane >> 2;
            uint32_t a[4][4], b[4][2];
#pragma unroll
            for (int mf = 0; mf < 4; mf++) {
                int r0 = wm * 64 + mf * 16 + row;
                a[mf][0] = *(const uint32_t*)&As[s][r0][k0];
                a[mf][1] = *(const uint32_t*)&As[s][r0 + 8][k0];
                a[mf][2] = *(const uint32_t*)&As[s][r0][k0 + 8];
                a[mf][3] = *(const uint32_t*)&As[s][r0 + 8][k0 + 8];
            }
#pragma unroll
            for (int nf = 0; nf < 4; nf++) {
                int n0 = wn * 32 + nf * 8 + row;
                b[nf][0] = *(const uint32_t*)&Bs[s][n0][k0];
                b[nf][1] = *(const uint32_t*)&Bs[s][n0][k0 + 8];
            }
#pragma unroll
            for (int mf = 0; mf < 4; mf++)
#pragma unroll
                for (int nf = 0; nf < 4; nf++)
                    mma16816(acc[mf][nf], a[mf], b[nf]);
        }
        __syncthreads();
    }

#pragma unroll
    for (int mf = 0; mf < 4; mf++) {
#pragma unroll
        for (int nf = 0; nf < 4; nf++) {
            int r0 = bm + wm * 64 + mf * 16 + (lane >> 2);
            int c0 = bn + wn * 32 + nf * 8 + ((lane & 3) << 1);
            float2 bo = *(const float2*)(bias + c0);
            float2 o0, o1;
            o0.x = acc[mf][nf][0] + bo.x;
            o0.y = acc[mf][nf][1] + bo.y;
            o1.x = acc[mf][nf][2] + bo.x;
            o1.y = acc[mf][nf][3] + bo.y;
            *(float2*)(C + (size_t)r0 * N + c0)       = o0;
            *(float2*)(C + (size_t)(r0 + 8) * N + c0) = o1;
        }
    }
}

// ---------------------------------------------------------------------------
// HMMA flash attention: 128q x (b,h) per CTA, 16 key-tiles of 128.
// Q in registers (split hi/lo), K/V split tiles double-buffered in smem.
// S = QhKh + QhKl + QlKh ; O = PhVh + PhVl + PlVh (P split in registers).
// ---------------------------------------------------------------------------
#define SK    72                      // smem row stride (elems)
#define ARR_E (128 * SK)              // 9216 elems per array
#define ATT_SMEM_BYTES (2 * 4 * ARR_E * 2)   // 147456

__global__ __launch_bounds__(256) void attn_mma(
    const bf16* __restrict__ qh, const bf16* __restrict__ ql,
    const bf16* __restrict__ kh, const bf16* __restrict__ kl,
    const bf16* __restrict__ vh, const bf16* __restrict__ vl,
    float* __restrict__ out)
{
    extern __shared__ bf16 smem[];    // [2][4][128][SK] : Kh,Kl,Vh,Vl
    const int t    = threadIdx.x;
    const int lane = t & 31;
    const int w    = t >> 5;          // 0..7, owns 16 q-rows
    const int bh   = blockIdx.x;      // 0..31
    const int qt   = blockIdx.y;      // 0..15
    const size_t seqbase = (size_t)bh * NSEQ;

    // ---- Q fragments (A operand), hi and lo, 4 k-steps of 16 ----
    uint32_t aqh[4][4], aql[4][4];
    {
        const int qrow0 = qt * 128 + w * 16;
        const bf16* qhb = qh + (seqbase + qrow0) * DH;
        const bf16* qlb = ql + (seqbase + qrow0) * DH;
        const int r = lane >> 2, c = (lane & 3) << 1;
#pragma unroll
        for (int ks = 0; ks < 4; ks++) {
            int d0 = ks * 16;
            aqh[ks][0] = *(const uint32_t*)(qhb + (size_t)r * DH + d0 + c);
            aqh[ks][1] = *(const uint32_t*)(qhb + (size_t)(r + 8) * DH + d0 + c);
            aqh[ks][2] = *(const uint32_t*)(qhb + (size_t)r * DH + d0 + c + 8);
            aqh[ks][3] = *(const uint32_t*)(qhb + (size_t)(r + 8) * DH + d0 + c + 8);
            aql[ks][0] = *(const uint32_t*)(qlb + (size_t)r * DH + d0 + c);
            aql[ks][1] = *(const uint32_t*)(qlb + (size_t)(r + 8) * DH + d0 + c);
            aql[ks][2] = *(const uint32_t*)(qlb + (size_t)r * DH + d0 + c + 8);
            aql[ks][3] = *(const uint32_t*)(qlb + (size_t)(r + 8) * DH + d0 + c + 8);
        }
    }

    float o[8][4];
#pragma unroll
    for (int db = 0; db < 8; db++)
#pragma unroll
        for (int q = 0; q < 4; q++) o[db][q] = 0.0f;
    float m0 = -1e30f, m1 = -1e30f, l0 = 0.0f, l1 = 0.0f;

    const bf16* garr[4] = { kh, kl, vh, vl };

    // fill one key tile (4 arrays x 128 rows x 128B) into buffer s
    auto fill = [&](int kt, int s) {
#pragma unroll
        for (int arr = 0; arr < 4; arr++) {
#pragma unroll
            for (int cc = 0; cc < 4; cc++) {
                int wi  = (cc << 8) + t;      // 0..1023
                int row = wi >> 3;
                int c16 = wi & 7;
                const bf16* g = garr[arr] + (seqbase + kt * 128 + row) * DH + (c16 << 3);
                cp16(smem_u32(&smem[(size_t)s * 4 * ARR_E + arr * ARR_E + row * SK + (c16 << 3)]), g);
            }
        }
    };

    fill(0, 0); CP_COMMIT();
    fill(1, 1); CP_COMMIT();

    for (int kt = 0; kt < NSEQ / 128; kt++) {
        if (kt < 15) asm volatile("cp.async.wait_group 1;" ::: "memory");
        else         asm volatile("cp.async.wait_group 0;" ::: "memory");
        __syncthreads();

        const int s = kt & 1;
        const bf16* sKh = smem + (size_t)s * 4 * ARR_E;
        const bf16* sKl = sKh + ARR_E;
        const bf16* sVh = sKh + 2 * ARR_E;
        const bf16* sVl = sKh + 3 * ARR_E;

        // ---- S = Q K^T (scaled later), 16 n-blocks of 8 keys ----
        float sf[16][4];
#pragma unroll
        for (int nb = 0; nb < 16; nb++) {
            sf[nb][0] = sf[nb][1] = sf[nb][2] = sf[nb][3] = 0.0f;
            const int key = nb * 8 + (lane >> 2);
            const int kc  = (lane & 3) << 1;
#pragma unroll
            for (int ks = 0; ks < 4; ks++) {
                uint32_t b_h[2], b_l[2];
                b_h[0] = *(const uint32_t*)&sKh[key * SK + ks * 16 + kc];
                b_h[1] = *(const uint32_t*)&sKh[key * SK + ks * 16 + kc + 8];
                b_l[0] = *(const uint32_t*)&sKl[key * SK + ks * 16 + kc];
                b_l[1] = *(const uint32_t*)&sKl[key * SK + ks * 16 + kc + 8];
                mma16816(sf[nb], aqh[ks], b_h);
                mma16816(sf[nb], aqh[ks], b_l);
                mma16816(sf[nb], aql[ks], b_h);
            }
        }

        // ---- softmax (online), rows: r_lo = lane>>2, r_hi = +8 ----
        float mt0 = -1e30f, mt1 = -1e30f;
#pragma unroll
        for (int nb = 0; nb < 16; nb++) {
            sf[nb][0] *= ATTN_SCALE; sf[nb][1] *= ATTN_SCALE;
            sf[nb][2] *= ATTN_SCALE; sf[nb][3] *= ATTN_SCALE;
            mt0 = fmaxf(mt0, fmaxf(sf[nb][0], sf[nb][1]));
            mt1 = fmaxf(mt1, fmaxf(sf[nb][2], sf[nb][3]));
        }
        mt0 = fmaxf(mt0, __shfl_xor_sync(0xffffffffu, mt0, 1));
        mt0 = fmaxf(mt0, __shfl_xor_sync(0xffffffffu, mt0, 2));
        mt1 = fmaxf(mt1, __shfl_xor_sync(0xffffffffu, mt1, 1));
        mt1 = fmaxf(mt1, __shfl_xor_sync(0xffffffffu, mt1, 2));

        const float mn0 = fmaxf(m0, mt0), mn1 = fmaxf(m1, mt1);
        const float corr0 = __expf(m0 - mn0), corr1 = __expf(m1 - mn1);
        m0 = mn0; m1 = mn1;

        float rs0 = 0.0f, rs1 = 0.0f;
        uint32_t pfh[16][2], pfl[16][2];
#pragma unroll
        for (int nb = 0; nb < 16; nb++) {
            float p0 = __expf(sf[nb][0] - mn0);
            float p1 = __expf(sf[nb][1] - mn0);
            float p2 = __expf(sf[nb][2] - mn1);
            float p3 = __expf(sf[nb][3] - mn1);
            rs0 += p0 + p1; rs1 += p2 + p3;
            float r0, r1, r2, r3;
            pfh[nb][0] = pack_split(p0, p1, r0, r1);
            pfh[nb][1] = pack_split(p2, p3, r2, r3);
            pfl[nb][0] = pack_only(r0, r1);
            pfl[nb][1] = pack_only(r2, r3);
        }
        rs0 += __shfl_xor_sync(0xffffffffu, rs0, 1);
        rs0 += __shfl_xor_sync(0xffffffffu, rs0, 2);
        rs1 += __shfl_xor_sync(0xffffffffu, rs1, 1);
        rs1 += __shfl_xor_sync(0xffffffffu, rs1, 2);
        l0 = l0 * corr0 + rs0;
        l1 = l1 * corr1 + rs1;
#pragma unroll
        for (int db = 0; db < 8; db++) {
            o[db][0] *= corr0; o[db][1] *= corr0;
            o[db][2] *= corr1; o[db][3] *= corr1;
        }

        // ---- O += P V : 8 k-steps of 16 keys ----
        // ldmatrix addr pieces (per thread, constant across kk/dp deltas)
        const int lm_key = (lane & 7) + ((lane >> 3) & 1) * 8;   // row within 16-key group
        const int lm_d   = (lane >> 4) * 8;                      // 0 or 8
#pragma unroll
        for (int kk = 0; kk < 8; kk++) {
            uint32_t aph[4] = { pfh[2 * kk][0], pfh[2 * kk][1],
                                pfh[2 * kk + 1][0], pfh[2 * kk + 1][1] };
            uint32_t apl[4] = { pfl[2 * kk][0], pfl[2 * kk][1],
                                pfl[2 * kk + 1][0], pfl[2 * kk + 1][1] };
#pragma unroll
            for (int dp = 0; dp < 4; dp++) {
                const int key = kk * 16 + lm_key;
                const int d0  = dp * 16 + lm_d;
                uint32_t vh0, vh1, vh2, vh3, vl0, vl1, vl2, vl3;
                ldsm_x4_t(vh0, vh1, vh2, vh3, smem_u32(&sVh[key * SK + d0]));
                ldsm_x4_t(vl0, vl1, vl2, vl3, smem_u32(&sVl[key * SK + d0]));
                uint32_t bh_a[2] = { vh0, vh1 }, bh_b[2] = { vh2, vh3 };
                uint32_t bl_a[2] = { vl0, vl1 }, bl_b[2] = { vl2, vl3 };
                mma16816(o[2 * dp],     aph, bh_a);
                mma16816(o[2 * dp],     aph, bl_a);
                mma16816(o[2 * dp],     apl, bh_a);
                mma16816(o[2 * dp + 1], aph, bh_b);
                mma16816(o[2 * dp + 1], aph, bl_b);
                mma16816(o[2 * dp + 1], apl, bh_b);
            }
        }

        __syncthreads();
        if (kt + 2 < NSEQ / 128) { fill(kt + 2, s); CP_COMMIT(); }
    }

    // ---- epilogue ----
    const float inv0 = 1.0f / l0, inv1 = 1.0f / l1;
    const int b = bh >> 4, h = bh & 15;
    const int q0 = qt * 128 + w * 16 + (lane >> 2);
#pragma unroll
    for (int db = 0; db < 8; db++) {
        int d0 = db * 8 + ((lane & 3) << 1);
        float2 x0, x1;
        x0.x = o[db][0] * inv0; x0.y = o[db][1] * inv0;
        x1.x = o[db][2] * inv1; x1.y = o[db][3] * inv1;
        *(float2*)(out + ((size_t)(b * NSEQ + q0) * EMBED) + h * DH + d0)       = x0;
        *(float2*)(out + ((size_t)(b * NSEQ + q0 + 8) * EMBED) + h * DH + d0)   = x1;
    }
}

// ---------------------------------------------------------------------------
extern "C" void kernel_launch(void* const* d_in, const int* in_sizes, int n_in,
                              void* d_out, int out_size)
{
    const float* x      = (const float*)d_in[0];
    const float* w_qkv  = (const float*)d_in[1];
    const float* b_qkv  = (const float*)d_in[2];
    const float* w_proj = (const float*)d_in[3];
    const float* b_proj = (const float*)d_in[4];
    float* out = (float*)d_out;

    float* qkv; cudaGetSymbolAddress((void**)&qkv, g_qkv);
    float* att; cudaGetSymbolAddress((void**)&att, g_att);
    bf16 *x3, *wq3, *at3, *wp3, *qh, *ql, *kh, *kl, *vh, *vl;
    cudaGetSymbolAddress((void**)&x3,  g_x3);
    cudaGetSymbolAddress((void**)&wq3, g_wq3);
    cudaGetSymbolAddress((void**)&at3, g_at3);
    cudaGetSymbolAddress((void**)&wp3, g_wp3);
    cudaGetSymbolAddress((void**)&qh,  g_qh);
    cudaGetSymbolAddress((void**)&ql,  g_ql);
    cudaGetSymbolAddress((void**)&kh,  g_kh);
    cudaGetSymbolAddress((void**)&kl,  g_kl);
    cudaGetSymbolAddress((void**)&vh,  g_vh);
    cudaGetSymbolAddress((void**)&vl,  g_vl);

    cudaFuncSetAttribute(attn_mma,
                         cudaFuncAttributeMaxDynamicSharedMemorySize, ATT_SMEM_BYTES);

    // split inputs for QKV GEMM
    {
        int n4 = ROWS * EMBED / 4;
        split3_kernel<<<(n4 + 255) / 256, 256>>>(x, x3, n4, 0);
        int m4 = QKV_COLS * EMBED / 4;
        split3_kernel<<<(m4 + 255) / 256, 256>>>(w_qkv, wq3, m4, 1);
    }

    // 1) QKV projection
    gemm_mma<<<dim3(QKV_COLS / 128, ROWS / 128), 256>>>(
        x3, wq3, b_qkv, qkv, ROWS, QKV_COLS);

    // 2) convert qkv -> head-major split bf16, then HMMA flash attention
    {
        int n4 = ROWS * EMBED / 4;
        split_qkv<<<(n4 + 255) / 256, 256>>>(qkv, qh, ql, 0);
        split_qkv<<<(n4 + 255) / 256, 256>>>(qkv, kh, kl, 1);
        split_qkv<<<(n4 + 255) / 256, 256>>>(qkv, vh, vl, 2);
    }
    attn_mma<<<dim3(BATCH * HEADS, NSEQ / 128), 256, ATT_SMEM_BYTES>>>(
        qh, ql, kh, kl, vh, vl, att);

    // split inputs for proj GEMM
    {
        int n4 = ROWS * EMBED / 4;
        split3_kernel<<<(n4 + 255) / 256, 256>>>(att, at3, n4, 0);
        int m4 = EMBED * EMBED / 4;
        split3_kernel<<<(m4 + 255) / 256, 256>>>(w_proj, wp3, m4, 1);
    }

    // 3) output projection
    gemm_mma<<<dim3(EMBED / 128, ROWS / 128), 256>>>(
        at3, wp3, b_proj, out, ROWS, EMBED);
}